// round 5
// baseline (speedup 1.0000x reference)
#include <cuda_runtime.h>
#include <math.h>

#define BB 8
#define LL 512
#define DD 128
#define UU 32
#define EPSF 1e-7f
#define NC 64            // 8-row chunks per batch
#define NC4 128          // 4-row chunks per batch
#define NSC 8            // superchunks of 64 rows per batch

// scratch (no allocs allowed)
__device__ float g_qs[BB*LL];
__device__ float g_ks[BB*LL];
__device__ float g_ek[BB*LL];
__device__ float g_T8  [BB*NC*DD];      // 8-row sums of x
__device__ float g_T8e [BB*NC*DD];      // 8-row sums of ek*x
__device__ float g_T4h [BB*NC*DD];      // first-4-row sums of x (per 8-chunk)
__device__ float g_T4he[BB*NC*DD];      // first-4-row sums of ek*x
__device__ float g_SO0[BB*NSC*DD];      // exclusive superchunk offsets (x)
__device__ float g_SO1[BB*NSC*DD];      // exclusive superchunk offsets (ek*x)
__device__ float g_P0[BB*(LL+1)*DD];    // prefix of x over s
__device__ float g_P1[BB*(LL+1)*DD];    // prefix of ek*x over s
__device__ float g_A[BB*LL];            // exp(qc-m)/Z
__device__ float g_E[BB*LL];            // exp(-m)/Z

// ---------------------------------------------------------------------------
// K1: fold weights (per-block, smem) + warp-per-token scalars + chunk sums.
//     grid=512, blk=256.  blockIdx = b*64 + c8
// ---------------------------------------------------------------------------
__global__ __launch_bounds__(256)
void k1(const float* __restrict__ x,
        const float* __restrict__ Wt, const float* __restrict__ Wx,
        const float* __restrict__ Wa) {
    int warp = threadIdx.x >> 5;
    int lane = threadIdx.x & 31;
    int token = blockIdx.x * 8 + warp;          // 8 consecutive rows, same batch

    __shared__ __align__(16) float swt[DD], swx[DD];
    __shared__ __align__(16) float srow[8*DD];
    __shared__ float sek[8];

    // fold (redundant per block; weight lines L1/L2-hot)
    if (threadIdx.x < DD) {
        int d = threadIdx.x;
        float at = 0.f, ax = 0.f;
#pragma unroll
        for (int u = 0; u < UU; u++) {
            float wa = __ldg(Wa + u);
            at = fmaf(__ldg(Wt + d*UU + u), wa, at);
            ax = fmaf(__ldg(Wx + d*UU + u), wa, ax);
        }
        swt[d] = at;
        swx[d] = ax;
    }

    const float4* xr = reinterpret_cast<const float4*>(x + (size_t)token * DD);
    float4 xv = xr[lane];
    reinterpret_cast<float4*>(srow)[warp*32 + lane] = xv;
    __syncthreads();

    float4 wt = reinterpret_cast<const float4*>(swt)[lane];
    float4 wx = reinterpret_cast<const float4*>(swx)[lane];
    float q = xv.x*wt.x + xv.y*wt.y + xv.z*wt.z + xv.w*wt.w;
    float k = xv.x*wx.x + xv.y*wx.y + xv.z*wx.z + xv.w*wx.w;
#pragma unroll
    for (int o = 16; o; o >>= 1) {
        q += __shfl_down_sync(0xFFFFFFFFu, q, o);
        k += __shfl_down_sync(0xFFFFFFFFu, k, o);
    }
    if (lane == 0) {
        float e = expf(k);
        g_qs[token] = q;
        g_ks[token] = k;
        g_ek[token] = e;
        sek[warp] = e;
    }
    __syncthreads();

    if (threadIdx.x < DD) {
        int d = threadIdx.x;
        float a0 = 0.f, a1 = 0.f, b0 = 0.f, b1 = 0.f;
#pragma unroll
        for (int w = 0; w < 4; w++) {
            float v = srow[w*DD + d];
            a0 += v;
            a1 = fmaf(sek[w], v, a1);
        }
#pragma unroll
        for (int w = 4; w < 8; w++) {
            float v = srow[w*DD + d];
            b0 += v;
            b1 = fmaf(sek[w], v, b1);
        }
        size_t o = (size_t)blockIdx.x * DD + d;
        g_T4h [o] = a0;
        g_T4he[o] = a1;
        g_T8  [o] = a0 + b0;
        g_T8e [o] = a1 + b1;
    }
}

// ---------------------------------------------------------------------------
// K2: per-batch: scan(ek) + window max + A/E scalars + superchunk offsets.
//     grid=8, blk=512
// ---------------------------------------------------------------------------
__global__ __launch_bounds__(512, 1)
void k2(const float* __restrict__ bh, const float* __restrict__ Wa,
        const float* __restrict__ ba) {
    int b   = blockIdx.x;
    int tid = threadIdx.x;

    __shared__ float sks[LL];
    __shared__ float scan[2][LL];
    __shared__ float cmax[LL/16];
    __shared__ float s8[2][NSC][DD];
    __shared__ float sc_c;

    sks[tid]     = g_ks[b*LL + tid];
    scan[0][tid] = g_ek[b*LL + tid];
    if (tid == 0) {
        float c = __ldg(ba);
#pragma unroll
        for (int u = 0; u < UU; u++) c = fmaf(__ldg(bh + u), __ldg(Wa + u), c);
        sc_c = c;
    }
    __syncthreads();

    if (tid < LL/16) {
        float m = sks[tid*16];
#pragma unroll
        for (int i = 1; i < 16; i++) m = fmaxf(m, sks[tid*16 + i]);
        cmax[tid] = m;
    }

    // superchunk sums from T8
    {
        int g = tid >> 7, d = tid & (DD-1);
#pragma unroll
        for (int q = g; q < NSC; q += 4) {
            float a0 = 0.f, a1 = 0.f;
#pragma unroll
            for (int j = 0; j < 8; j++) {
                a0 += g_T8 [(size_t)(b*NC + q*8 + j)*DD + d];
                a1 += g_T8e[(size_t)(b*NC + q*8 + j)*DD + d];
            }
            s8[0][q][d] = a0;
            s8[1][q][d] = a1;
        }
    }

    // Hillis-Steele inclusive scan of ek (9 steps)
    int cur = 0;
#pragma unroll
    for (int off = 1; off < LL; off <<= 1) {
        __syncthreads();
        float v = scan[cur][tid];
        if (tid >= off) v += scan[cur][tid - off];
        scan[cur ^ 1][tid] = v;
        cur ^= 1;
    }
    __syncthreads();

    // exclusive superchunk offsets -> global
    if (tid < DD) {
        int d = tid;
        float r0 = 0.f, r1 = 0.f;
#pragma unroll
        for (int sc = 0; sc < NSC; sc++) {
            g_SO0[(size_t)(b*NSC + sc)*DD + d] = r0;
            g_SO1[(size_t)(b*NSC + sc)*DD + d] = r1;
            r0 += s8[0][sc][d];
            r1 += s8[1][sc][d];
        }
    }

    // per-query softmax scalars
    {
        int t  = tid;
        int lo = max(0, t - 63);
        int hi = min(LL - 1, t + 64);
        int wc = hi - lo + 1;

        float wm = -INFINITY;
        int c0 = lo >> 4, c1 = hi >> 4;
        int e0 = (c0 + 1) << 4;
        for (int s = lo; s < e0; s++) wm = fmaxf(wm, sks[s]);
        for (int c = c0 + 1; c < c1; c++) wm = fmaxf(wm, cmax[c]);
        for (int s = c1 << 4; s <= hi; s++) wm = fmaxf(wm, sks[s]);

        float qc = g_qs[b*LL + t] + sc_c;
        float m  = fmaxf(0.f, qc + wm);     // masked entries score 0, always present
        float A  = expf(qc - m);
        float E  = expf(-m);
        float S1 = scan[cur][hi] - (lo > 0 ? scan[cur][lo-1] : 0.f);
        float Z  = A * S1 + E * (float)(LL - wc) + EPSF;
        float iv = 1.f / Z;
        g_A[b*LL + t] = A * iv;
        g_E[b*LL + t] = E * iv;
    }
}

// ---------------------------------------------------------------------------
// K3p: materialize P0/P1. Block = (b, 4-row chunk). grid=1024, blk=128
// ---------------------------------------------------------------------------
__global__ __launch_bounds__(128)
void k3p(const float* __restrict__ x) {
    int blk = blockIdx.x;
    int b   = blk >> 7;
    int c4  = blk & (NC4-1);
    int d   = threadIdx.x;

    int c8 = c4 >> 1;            // parent 8-row chunk (0..63)
    int sc = c4 >> 4;            // superchunk (0..7)
    int j0 = sc << 3;            // first 8-chunk of superchunk

    float off0 = g_SO0[(size_t)(b*NSC + sc)*DD + d];
    float off1 = g_SO1[(size_t)(b*NSC + sc)*DD + d];
#pragma unroll 7
    for (int j = j0; j < c8; j++) {          // <=7 independent loads
        off0 += g_T8 [(size_t)(b*NC + j)*DD + d];
        off1 += g_T8e[(size_t)(b*NC + j)*DD + d];
    }
    if (c4 & 1) {
        off0 += g_T4h [(size_t)(b*NC + c8)*DD + d];
        off1 += g_T4he[(size_t)(b*NC + c8)*DD + d];
    }

    const float* xb = x + (size_t)b * LL * DD;
    int s0 = c4 * 4;
    float xr[4], er[4];
#pragma unroll
    for (int i = 0; i < 4; i++) {
        xr[i] = __ldg(xb + (size_t)(s0 + i)*DD + d);
        er[i] = __ldg(g_ek + b*LL + s0 + i);
    }

    size_t base = (size_t)b * (LL+1) * DD;
    if (c4 == 0) {
        g_P0[base + d] = 0.f;
        g_P1[base + d] = 0.f;
    }
#pragma unroll
    for (int i = 0; i < 4; i++) {
        off0 += xr[i];
        off1 = fmaf(er[i], xr[i], off1);
        g_P0[base + (size_t)(s0 + i + 1)*DD + d] = off0;
        g_P1[base + (size_t)(s0 + i + 1)*DD + d] = off1;
    }
}

// ---------------------------------------------------------------------------
// K4: epilogue, float2 per thread. grid=1024, blk=256
// ---------------------------------------------------------------------------
__global__ __launch_bounds__(256)
void k4(float* __restrict__ out) {
    int idx = blockIdx.x * blockDim.x + threadIdx.x;   // 0 .. BB*LL*DD/2-1
    int bt  = idx >> 6;                                // 64 float2 per row
    int d2  = idx & 63;
    int b   = bt >> 9;
    int t   = bt & (LL-1);

    int lo = max(0, t - 63);
    int hi = min(LL - 1, t + 64);

    size_t base = (size_t)b * (LL+1) * DD;
    const float2* P1 = reinterpret_cast<const float2*>(g_P1);
    const float2* P0 = reinterpret_cast<const float2*>(g_P0);

    size_t rHi = (base + (size_t)(hi+1)*DD) >> 1;
    size_t rLo = (base + (size_t)lo*DD) >> 1;
    size_t rTt = (base + (size_t)LL*DD) >> 1;

    float2 v1h = P1[rHi + d2], v1l = P1[rLo + d2];
    float2 v0h = P0[rHi + d2], v0l = P0[rLo + d2];
    float2 tot = P0[rTt + d2];
    float  A   = g_A[bt];
    float  E   = g_E[bt];

    float2 o;
    o.x = A*(v1h.x - v1l.x) + E*(tot.x - (v0h.x - v0l.x));
    o.y = A*(v1h.y - v1l.y) + E*(tot.y - (v0h.y - v0l.y));

    reinterpret_cast<float2*>(out)[idx] = o;
}

extern "C" void kernel_launch(void* const* d_in, const int* in_sizes, int n_in,
                              void* d_out, int out_size) {
    const float* x  = (const float*)d_in[0];   // [B,L,D]
    const float* Wt = (const float*)d_in[1];   // [D,U]
    const float* Wx = (const float*)d_in[2];   // [D,U]
    const float* bh = (const float*)d_in[3];   // [U]
    const float* Wa = (const float*)d_in[4];   // [U,1]
    const float* ba = (const float*)d_in[5];   // [1]
    float* out = (float*)d_out;                // [B,L,D]

    k1<<<BB*LL/8, 256>>>(x, Wt, Wx, Wa);
    k2<<<BB, 512>>>(bh, Wa, ba);
    k3p<<<BB*NC4, DD>>>(x);
    k4<<<(BB*LL*DD/2)/256, 256>>>(out);
}

// round 6
// speedup vs baseline: 1.4451x; 1.4451x over previous
#include <cuda_runtime.h>
#include <math.h>

#define BB 8
#define LL 512
#define DD 128
#define UU 32
#define EPSF 1e-7f
#define NC 64            // 8-row chunks per batch
#define NC4 128          // 4-row chunks per batch
#define NSC 8            // superchunks of 64 rows per batch

// scratch (no allocs allowed)
__device__ __align__(16) float g_wtv[DD];
__device__ __align__(16) float g_wxv[DD];
__device__ float g_c;
__device__ float g_qs[BB*LL];
__device__ float g_ks[BB*LL];
__device__ float g_ek[BB*LL];
__device__ float g_T8  [BB*NC*DD];      // 8-row sums of x
__device__ float g_T8e [BB*NC*DD];      // 8-row sums of ek*x
__device__ float g_T4h [BB*NC*DD];      // first-4-row sums of x (per 8-chunk)
__device__ float g_T4he[BB*NC*DD];      // first-4-row sums of ek*x
__device__ float g_SO0[BB*NSC*DD];      // exclusive superchunk offsets (x)
__device__ float g_SO1[BB*NSC*DD];      // exclusive superchunk offsets (ek*x)
__device__ float g_P0[BB*(LL+1)*DD];    // prefix of x over s
__device__ float g_P1[BB*(LL+1)*DD];    // prefix of ek*x over s
__device__ float g_A[BB*LL];            // exp(qc-m)/Z
__device__ float g_E[BB*LL];            // exp(-m)/Z

// ---------------------------------------------------------------------------
// K0: fold weights (1 block, 128 thr)
// ---------------------------------------------------------------------------
__global__ void k0_fold(const float* __restrict__ Wt, const float* __restrict__ Wx,
                        const float* __restrict__ bh, const float* __restrict__ Wa,
                        const float* __restrict__ ba) {
    int d = threadIdx.x;
    float at = 0.f, ax = 0.f;
#pragma unroll
    for (int u = 0; u < UU; u++) {
        float wa = Wa[u];
        at += Wt[d*UU + u] * wa;
        ax += Wx[d*UU + u] * wa;
    }
    g_wtv[d] = at;
    g_wxv[d] = ax;
    if (d == 0) {
        float c = ba[0];
#pragma unroll
        for (int u = 0; u < UU; u++) c += bh[u] * Wa[u];
        g_c = c;
    }
}

// ---------------------------------------------------------------------------
// K1: warp-per-token scalars + chunk-8 / half-chunk sums. grid=512, blk=256
// ---------------------------------------------------------------------------
__global__ __launch_bounds__(256)
void k1(const float* __restrict__ x) {
    int warp = threadIdx.x >> 5;
    int lane = threadIdx.x & 31;
    int token = blockIdx.x * 8 + warp;          // 8 consecutive rows, same batch

    const float4* xr = reinterpret_cast<const float4*>(x + (size_t)token * DD);
    float4 xv = xr[lane];
    float4 wt = reinterpret_cast<const float4*>(g_wtv)[lane];
    float4 wx = reinterpret_cast<const float4*>(g_wxv)[lane];
    float q = xv.x*wt.x + xv.y*wt.y + xv.z*wt.z + xv.w*wt.w;
    float k = xv.x*wx.x + xv.y*wx.y + xv.z*wx.z + xv.w*wx.w;
#pragma unroll
    for (int o = 16; o; o >>= 1) {
        q += __shfl_down_sync(0xFFFFFFFFu, q, o);
        k += __shfl_down_sync(0xFFFFFFFFu, k, o);
    }

    __shared__ __align__(16) float srow[8*DD];
    __shared__ float sek[8];
    reinterpret_cast<float4*>(srow)[warp*32 + lane] = xv;
    if (lane == 0) {
        float e = expf(k);
        g_qs[token] = q;
        g_ks[token] = k;
        g_ek[token] = e;
        sek[warp] = e;
    }
    __syncthreads();

    if (threadIdx.x < DD) {
        int d = threadIdx.x;
        float a0 = 0.f, a1 = 0.f, b0 = 0.f, b1 = 0.f;
#pragma unroll
        for (int w = 0; w < 4; w++) {
            float v = srow[w*DD + d];
            a0 += v;
            a1 = fmaf(sek[w], v, a1);
        }
#pragma unroll
        for (int w = 4; w < 8; w++) {
            float v = srow[w*DD + d];
            b0 += v;
            b1 = fmaf(sek[w], v, b1);
        }
        size_t o = (size_t)blockIdx.x * DD + d;
        g_T4h [o] = a0;
        g_T4he[o] = a1;
        g_T8  [o] = a0 + b0;
        g_T8e [o] = a1 + b1;
    }
}

// ---------------------------------------------------------------------------
// K2: per-batch: scan(ek) + window max + A/E scalars + superchunk offsets.
//     grid=8, blk=512
// ---------------------------------------------------------------------------
__global__ __launch_bounds__(512, 1)
void k2(void) {
    int b   = blockIdx.x;
    int tid = threadIdx.x;

    __shared__ float sks[LL];
    __shared__ float scan[2][LL];
    __shared__ float cmax[LL/16];
    __shared__ float s8[2][NSC][DD];

    sks[tid]     = g_ks[b*LL + tid];
    scan[0][tid] = g_ek[b*LL + tid];
    __syncthreads();

    if (tid < LL/16) {
        float m = sks[tid*16];
#pragma unroll
        for (int i = 1; i < 16; i++) m = fmaxf(m, sks[tid*16 + i]);
        cmax[tid] = m;
    }

    // superchunk sums from T8
    {
        int g = tid >> 7, d = tid & (DD-1);
#pragma unroll
        for (int q = g; q < NSC; q += 4) {
            float a0 = 0.f, a1 = 0.f;
#pragma unroll
            for (int j = 0; j < 8; j++) {
                a0 += g_T8 [(size_t)(b*NC + q*8 + j)*DD + d];
                a1 += g_T8e[(size_t)(b*NC + q*8 + j)*DD + d];
            }
            s8[0][q][d] = a0;
            s8[1][q][d] = a1;
        }
    }

    // Hillis-Steele inclusive scan of ek (9 steps)
    int cur = 0;
#pragma unroll
    for (int off = 1; off < LL; off <<= 1) {
        __syncthreads();
        float v = scan[cur][tid];
        if (tid >= off) v += scan[cur][tid - off];
        scan[cur ^ 1][tid] = v;
        cur ^= 1;
    }
    __syncthreads();

    // exclusive superchunk offsets -> global
    if (tid < DD) {
        int d = tid;
        float r0 = 0.f, r1 = 0.f;
#pragma unroll
        for (int sc = 0; sc < NSC; sc++) {
            g_SO0[(size_t)(b*NSC + sc)*DD + d] = r0;
            g_SO1[(size_t)(b*NSC + sc)*DD + d] = r1;
            r0 += s8[0][sc][d];
            r1 += s8[1][sc][d];
        }
    }

    // per-query softmax scalars
    {
        int t  = tid;
        int lo = max(0, t - 63);
        int hi = min(LL - 1, t + 64);
        int wc = hi - lo + 1;

        float wm = -INFINITY;
        int c0 = lo >> 4, c1 = hi >> 4;
        int e0 = (c0 + 1) << 4;
        for (int s = lo; s < e0; s++) wm = fmaxf(wm, sks[s]);
        for (int c = c0 + 1; c < c1; c++) wm = fmaxf(wm, cmax[c]);
        for (int s = c1 << 4; s <= hi; s++) wm = fmaxf(wm, sks[s]);

        float qc = g_qs[b*LL + t] + g_c;
        float m  = fmaxf(0.f, qc + wm);     // masked entries score 0, always present
        float A  = expf(qc - m);
        float E  = expf(-m);
        float S1 = scan[cur][hi] - (lo > 0 ? scan[cur][lo-1] : 0.f);
        float Z  = A * S1 + E * (float)(LL - wc) + EPSF;
        float iv = 1.f / Z;
        g_A[b*LL + t] = A * iv;
        g_E[b*LL + t] = E * iv;
    }
}

// ---------------------------------------------------------------------------
// K3p: materialize P0/P1. Block = (b, 4-row chunk). grid=1024, blk=128
// ---------------------------------------------------------------------------
__global__ __launch_bounds__(128)
void k3p(const float* __restrict__ x) {
    int blk = blockIdx.x;
    int b   = blk >> 7;
    int c4  = blk & (NC4-1);
    int d   = threadIdx.x;

    int c8 = c4 >> 1;            // parent 8-row chunk (0..63)
    int sc = c4 >> 4;            // superchunk (0..7)
    int j0 = sc << 3;            // first 8-chunk of superchunk

    float off0 = g_SO0[(size_t)(b*NSC + sc)*DD + d];
    float off1 = g_SO1[(size_t)(b*NSC + sc)*DD + d];
#pragma unroll 7
    for (int j = j0; j < c8; j++) {          // <=7 independent loads
        off0 += g_T8 [(size_t)(b*NC + j)*DD + d];
        off1 += g_T8e[(size_t)(b*NC + j)*DD + d];
    }
    if (c4 & 1) {
        off0 += g_T4h [(size_t)(b*NC + c8)*DD + d];
        off1 += g_T4he[(size_t)(b*NC + c8)*DD + d];
    }

    const float* xb = x + (size_t)b * LL * DD;
    int s0 = c4 * 4;
    float xr[4], er[4];
#pragma unroll
    for (int i = 0; i < 4; i++) {
        xr[i] = __ldg(xb + (size_t)(s0 + i)*DD + d);
        er[i] = __ldg(g_ek + b*LL + s0 + i);
    }

    size_t base = (size_t)b * (LL+1) * DD;
    if (c4 == 0) {
        g_P0[base + d] = 0.f;
        g_P1[base + d] = 0.f;
    }
#pragma unroll
    for (int i = 0; i < 4; i++) {
        off0 += xr[i];
        off1 = fmaf(er[i], xr[i], off1);
        g_P0[base + (size_t)(s0 + i + 1)*DD + d] = off0;
        g_P1[base + (size_t)(s0 + i + 1)*DD + d] = off1;
    }
}

// ---------------------------------------------------------------------------
// K4: epilogue, float2 per thread. grid=1024, blk=256
// ---------------------------------------------------------------------------
__global__ __launch_bounds__(256)
void k4(float* __restrict__ out) {
    int idx = blockIdx.x * blockDim.x + threadIdx.x;   // 0 .. BB*LL*DD/2-1
    int bt  = idx >> 6;                                // 64 float2 per row
    int d2  = idx & 63;
    int b   = bt >> 9;
    int t   = bt & (LL-1);

    int lo = max(0, t - 63);
    int hi = min(LL - 1, t + 64);

    size_t base = (size_t)b * (LL+1) * DD;
    const float2* P1 = reinterpret_cast<const float2*>(g_P1);
    const float2* P0 = reinterpret_cast<const float2*>(g_P0);

    size_t rHi = (base + (size_t)(hi+1)*DD) >> 1;
    size_t rLo = (base + (size_t)lo*DD) >> 1;
    size_t rTt = (base + (size_t)LL*DD) >> 1;

    float2 v1h = P1[rHi + d2], v1l = P1[rLo + d2];
    float2 v0h = P0[rHi + d2], v0l = P0[rLo + d2];
    float2 tot = P0[rTt + d2];
    float  A   = g_A[bt];
    float  E   = g_E[bt];

    float2 o;
    o.x = A*(v1h.x - v1l.x) + E*(tot.x - (v0h.x - v0l.x));
    o.y = A*(v1h.y - v1l.y) + E*(tot.y - (v0h.y - v0l.y));

    reinterpret_cast<float2*>(out)[idx] = o;
}

extern "C" void kernel_launch(void* const* d_in, const int* in_sizes, int n_in,
                              void* d_out, int out_size) {
    const float* x  = (const float*)d_in[0];   // [B,L,D]
    const float* Wt = (const float*)d_in[1];   // [D,U]
    const float* Wx = (const float*)d_in[2];   // [D,U]
    const float* bh = (const float*)d_in[3];   // [U]
    const float* Wa = (const float*)d_in[4];   // [U,1]
    const float* ba = (const float*)d_in[5];   // [1]
    float* out = (float*)d_out;                // [B,L,D]

    k0_fold<<<1, DD>>>(Wt, Wx, bh, Wa, ba);
    k1<<<BB*LL/8, 256>>>(x);
    k2<<<BB, 512>>>();
    k3p<<<BB*NC4, DD>>>(x);
    k4<<<(BB*LL*DD/2)/256, 256>>>(out);
}

// round 7
// speedup vs baseline: 1.4738x; 1.0199x over previous
#include <cuda_runtime.h>
#include <math.h>

#define BB 8
#define LL 512
#define DD 128
#define UU 32
#define EPSF 1e-7f
#define NC 64            // 8-row chunks per batch
#define NSC 8            // superchunks of 64 rows per batch

// scratch (no allocs allowed)
__device__ __align__(16) float g_wtv[DD];
__device__ __align__(16) float g_wxv[DD];
__device__ float g_c;
__device__ float g_qs[BB*LL];
__device__ float g_ks[BB*LL];
__device__ float g_ek[BB*LL];
__device__ float g_T8 [BB*NC*DD];       // 8-row sums of x
__device__ float g_T8e[BB*NC*DD];       // 8-row sums of ek*x
__device__ float g_C0[BB*(NC+1)*DD];    // exclusive chunk prefix of x
__device__ float g_C1[BB*(NC+1)*DD];    // exclusive chunk prefix of ek*x
__device__ float g_A[BB*LL];            // exp(qc-m)/Z
__device__ float g_E[BB*LL];            // exp(-m)/Z

// ---------------------------------------------------------------------------
// K0: fold weights (1 block, 128 thr)
// ---------------------------------------------------------------------------
__global__ void k0_fold(const float* __restrict__ Wt, const float* __restrict__ Wx,
                        const float* __restrict__ bh, const float* __restrict__ Wa,
                        const float* __restrict__ ba) {
    int d = threadIdx.x;
    float at = 0.f, ax = 0.f;
#pragma unroll
    for (int u = 0; u < UU; u++) {
        float wa = Wa[u];
        at += Wt[d*UU + u] * wa;
        ax += Wx[d*UU + u] * wa;
    }
    g_wtv[d] = at;
    g_wxv[d] = ax;
    if (d == 0) {
        float c = ba[0];
#pragma unroll
        for (int u = 0; u < UU; u++) c += bh[u] * Wa[u];
        g_c = c;
    }
}

// ---------------------------------------------------------------------------
// K1: warp-per-token scalars + chunk-8 sums. grid=512, blk=256
// ---------------------------------------------------------------------------
__global__ __launch_bounds__(256)
void k1(const float* __restrict__ x) {
    int warp = threadIdx.x >> 5;
    int lane = threadIdx.x & 31;
    int token = blockIdx.x * 8 + warp;          // 8 consecutive rows, same batch

    const float4* xr = reinterpret_cast<const float4*>(x + (size_t)token * DD);
    float4 xv = xr[lane];
    float4 wt = reinterpret_cast<const float4*>(g_wtv)[lane];
    float4 wx = reinterpret_cast<const float4*>(g_wxv)[lane];
    float q = xv.x*wt.x + xv.y*wt.y + xv.z*wt.z + xv.w*wt.w;
    float k = xv.x*wx.x + xv.y*wx.y + xv.z*wx.z + xv.w*wx.w;
#pragma unroll
    for (int o = 16; o; o >>= 1) {
        q += __shfl_down_sync(0xFFFFFFFFu, q, o);
        k += __shfl_down_sync(0xFFFFFFFFu, k, o);
    }

    __shared__ __align__(16) float srow[8*DD];
    __shared__ float sek[8];
    reinterpret_cast<float4*>(srow)[warp*32 + lane] = xv;
    if (lane == 0) {
        float e = expf(k);
        g_qs[token] = q;
        g_ks[token] = k;
        g_ek[token] = e;
        sek[warp] = e;
    }
    __syncthreads();

    if (threadIdx.x < DD) {
        int d = threadIdx.x;
        float s0 = 0.f, s1 = 0.f;
#pragma unroll
        for (int w = 0; w < 8; w++) {
            float v = srow[w*DD + d];
            s0 += v;
            s1 = fmaf(sek[w], v, s1);
        }
        size_t o = (size_t)blockIdx.x * DD + d;
        g_T8 [o] = s0;
        g_T8e[o] = s1;
    }
}

// ---------------------------------------------------------------------------
// K2: per-batch: scan(ek) + window max + A/E scalars + chunk prefixes C0/C1.
//     grid=8, blk=512
// ---------------------------------------------------------------------------
__global__ __launch_bounds__(512, 1)
void k2(void) {
    int b   = blockIdx.x;
    int tid = threadIdx.x;

    __shared__ float sks[LL];
    __shared__ float scan[2][LL];
    __shared__ float cmax[LL/16];
    __shared__ float s8[2][NSC][DD];

    sks[tid]     = g_ks[b*LL + tid];
    scan[0][tid] = g_ek[b*LL + tid];
    __syncthreads();

    if (tid < LL/16) {
        float m = sks[tid*16];
#pragma unroll
        for (int i = 1; i < 16; i++) m = fmaxf(m, sks[tid*16 + i]);
        cmax[tid] = m;
    }

    // superchunk sums from T8
    {
        int g = tid >> 7, d = tid & (DD-1);
#pragma unroll
        for (int q = g; q < NSC; q += 4) {
            float a0 = 0.f, a1 = 0.f;
#pragma unroll
            for (int j = 0; j < 8; j++) {
                a0 += g_T8 [(size_t)(b*NC + q*8 + j)*DD + d];
                a1 += g_T8e[(size_t)(b*NC + q*8 + j)*DD + d];
            }
            s8[0][q][d] = a0;
            s8[1][q][d] = a1;
        }
    }

    // Hillis-Steele inclusive scan of ek (9 steps)
    int cur = 0;
#pragma unroll
    for (int off = 1; off < LL; off <<= 1) {
        __syncthreads();
        float v = scan[cur][tid];
        if (tid >= off) v += scan[cur][tid - off];
        scan[cur ^ 1][tid] = v;
        cur ^= 1;
    }
    __syncthreads();

    // exclusive chunk prefixes: group g handles superchunks 2g, 2g+1
    {
        int g = tid >> 7, d = tid & (DD-1);
#pragma unroll
        for (int ss = 0; ss < 2; ss++) {
            int sc = g*2 + ss;
            float r0 = 0.f, r1 = 0.f;
            for (int q = 0; q < sc; q++) { r0 += s8[0][q][d]; r1 += s8[1][q][d]; }
#pragma unroll
            for (int j = sc*8; j < sc*8 + 8; j++) {
                g_C0[(size_t)(b*(NC+1) + j)*DD + d] = r0;
                g_C1[(size_t)(b*(NC+1) + j)*DD + d] = r1;
                r0 += g_T8 [(size_t)(b*NC + j)*DD + d];
                r1 += g_T8e[(size_t)(b*NC + j)*DD + d];
            }
            if (sc == NSC-1) {
                g_C0[(size_t)(b*(NC+1) + NC)*DD + d] = r0;
                g_C1[(size_t)(b*(NC+1) + NC)*DD + d] = r1;
            }
        }
    }

    // per-query softmax scalars
    {
        int t  = tid;
        int lo = max(0, t - 63);
        int hi = min(LL - 1, t + 64);
        int wc = hi - lo + 1;

        float wm = -INFINITY;
        int c0 = lo >> 4, c1 = hi >> 4;
        int e0 = (c0 + 1) << 4;
        for (int s = lo; s < e0; s++) wm = fmaxf(wm, sks[s]);
        for (int c = c0 + 1; c < c1; c++) wm = fmaxf(wm, cmax[c]);
        for (int s = c1 << 4; s <= hi; s++) wm = fmaxf(wm, sks[s]);

        float qc = g_qs[b*LL + t] + g_c;
        float m  = fmaxf(0.f, qc + wm);     // masked entries score 0, always present
        float A  = expf(qc - m);
        float E  = expf(-m);
        float S1 = scan[cur][hi] - (lo > 0 ? scan[cur][lo-1] : 0.f);
        float Z  = A * S1 + E * (float)(LL - wc) + EPSF;
        float iv = 1.f / Z;
        g_A[b*LL + t] = A * iv;
        g_E[b*LL + t] = E * iv;
    }
}

// ---------------------------------------------------------------------------
// K3f: fused window-sum + output. Block = (b, 8-query group). grid=512, blk=128
//   W(t) = C[jh] + x[t0+64] - C[jl] - x[t0-64], then O(1) slides.
// ---------------------------------------------------------------------------
__global__ __launch_bounds__(128)
void k3f(const float* __restrict__ x, float* __restrict__ out) {
    int blk = blockIdx.x;
    int b   = blk >> 6;
    int t0  = (blk & 63) * 8;
    int d   = threadIdx.x;

    bool lo_act = (t0 >= 64);    // else window bottom pinned at 0 for all 8 queries
    bool hi_act = (t0 <= 440);   // else window top pinned at 511 for all 8 queries

    int jh = hi_act ? ((t0 + 64) >> 3) : NC;
    int jl = lo_act ? ((t0 - 64) >> 3) : 0;

    size_t cbase = (size_t)b * (NC+1) * DD;
    float V0 = __ldg(g_C0 + cbase + (size_t)jh*DD + d) - __ldg(g_C0 + cbase + (size_t)jl*DD + d);
    float V1 = __ldg(g_C1 + cbase + (size_t)jh*DD + d) - __ldg(g_C1 + cbase + (size_t)jl*DD + d);
    float tot = __ldg(g_C0 + cbase + (size_t)NC*DD + d);

    const float* xb  = x + (size_t)b * LL * DD;
    const float* ekb = g_ek + b*LL;

    if (hi_act) {
        float xv = __ldg(xb + (size_t)(t0+64)*DD + d);
        V0 += xv;
        V1 = fmaf(__ldg(ekb + t0 + 64), xv, V1);
    }
    if (lo_act) {
        float xv = __ldg(xb + (size_t)(t0-64)*DD + d);
        V0 -= xv;
        V1 = fmaf(-__ldg(ekb + t0 - 64), xv, V1);
    }

    {
        float A = __ldg(g_A + b*LL + t0);
        float E = __ldg(g_E + b*LL + t0);
        out[((size_t)b*LL + t0)*DD + d] = A*V1 + E*(tot - V0);
    }
#pragma unroll
    for (int i = 1; i < 8; i++) {
        int t = t0 + i;
        if (hi_act) {
            float xv = __ldg(xb + (size_t)(t+64)*DD + d);
            V0 += xv;
            V1 = fmaf(__ldg(ekb + t + 64), xv, V1);
        }
        if (lo_act) {
            float xv = __ldg(xb + (size_t)(t-64)*DD + d);
            V0 -= xv;
            V1 = fmaf(-__ldg(ekb + t - 64), xv, V1);
        }
        float A = __ldg(g_A + b*LL + t);
        float E = __ldg(g_E + b*LL + t);
        out[((size_t)b*LL + t)*DD + d] = A*V1 + E*(tot - V0);
    }
}

extern "C" void kernel_launch(void* const* d_in, const int* in_sizes, int n_in,
                              void* d_out, int out_size) {
    const float* x  = (const float*)d_in[0];   // [B,L,D]
    const float* Wt = (const float*)d_in[1];   // [D,U]
    const float* Wx = (const float*)d_in[2];   // [D,U]
    const float* bh = (const float*)d_in[3];   // [U]
    const float* Wa = (const float*)d_in[4];   // [U,1]
    const float* ba = (const float*)d_in[5];   // [1]
    float* out = (float*)d_out;                // [B,L,D]

    k0_fold<<<1, DD>>>(Wt, Wx, bh, Wa, ba);
    k1<<<BB*LL/8, 256>>>(x);
    k2<<<BB, 512>>>();
    k3f<<<BB*NC, DD>>>(x, out);
}

// round 8
// speedup vs baseline: 1.7551x; 1.1909x over previous
#include <cuda_runtime.h>
#include <math.h>

#define BB 8
#define LL 512
#define DD 128
#define UU 32
#define EPSF 1e-7f
#define NC 64            // 8-row chunks per batch
#define NSC 8            // superchunks of 64 rows per batch

// scratch (no allocs allowed)
__device__ __align__(16) float g_wtv[DD];
__device__ __align__(16) float g_wxv[DD];
__device__ float g_c;
__device__ float g_qs[BB*LL];
__device__ float g_ks[BB*LL];
__device__ float g_ek[BB*LL];
__device__ float g_T8 [BB*NC*DD];       // 8-row sums of x
__device__ float g_T8e[BB*NC*DD];       // 8-row sums of ek*x
__device__ float g_C0[BB*(NC+1)*DD];    // exclusive chunk prefix of x
__device__ float g_C1[BB*(NC+1)*DD];    // exclusive chunk prefix of ek*x
__device__ float g_A[BB*LL];            // exp(qc-m)/Z
__device__ float g_E[BB*LL];            // exp(-m)/Z

// ---------------------------------------------------------------------------
// K0: fold weights (1 block, 128 thr)
// ---------------------------------------------------------------------------
__global__ void k0_fold(const float* __restrict__ Wt, const float* __restrict__ Wx,
                        const float* __restrict__ bh, const float* __restrict__ Wa,
                        const float* __restrict__ ba) {
    int d = threadIdx.x;
    float at = 0.f, ax = 0.f;
#pragma unroll
    for (int u = 0; u < UU; u++) {
        float wa = Wa[u];
        at += Wt[d*UU + u] * wa;
        ax += Wx[d*UU + u] * wa;
    }
    g_wtv[d] = at;
    g_wxv[d] = ax;
    if (d == 0) {
        float c = ba[0];
#pragma unroll
        for (int u = 0; u < UU; u++) c += bh[u] * Wa[u];
        g_c = c;
    }
}

// ---------------------------------------------------------------------------
// K1: warp-per-token scalars + chunk-8 sums. grid=512, blk=256
// ---------------------------------------------------------------------------
__global__ __launch_bounds__(256)
void k1(const float* __restrict__ x) {
    int warp = threadIdx.x >> 5;
    int lane = threadIdx.x & 31;
    int token = blockIdx.x * 8 + warp;          // 8 consecutive rows, same batch

    const float4* xr = reinterpret_cast<const float4*>(x + (size_t)token * DD);
    float4 xv = xr[lane];
    float4 wt = reinterpret_cast<const float4*>(g_wtv)[lane];
    float4 wx = reinterpret_cast<const float4*>(g_wxv)[lane];
    float q = xv.x*wt.x + xv.y*wt.y + xv.z*wt.z + xv.w*wt.w;
    float k = xv.x*wx.x + xv.y*wx.y + xv.z*wx.z + xv.w*wx.w;
#pragma unroll
    for (int o = 16; o; o >>= 1) {
        q += __shfl_down_sync(0xFFFFFFFFu, q, o);
        k += __shfl_down_sync(0xFFFFFFFFu, k, o);
    }

    __shared__ __align__(16) float srow[8*DD];
    __shared__ float sek[8];
    reinterpret_cast<float4*>(srow)[warp*32 + lane] = xv;
    if (lane == 0) {
        float e = expf(k);
        g_qs[token] = q;
        g_ks[token] = k;
        g_ek[token] = e;
        sek[warp] = e;
    }
    __syncthreads();

    if (threadIdx.x < DD) {
        int d = threadIdx.x;
        float s0 = 0.f, s1 = 0.f;
#pragma unroll
        for (int w = 0; w < 8; w++) {
            float v = srow[w*DD + d];
            s0 += v;
            s1 = fmaf(sek[w], v, s1);
        }
        size_t o = (size_t)blockIdx.x * DD + d;
        g_T8 [o] = s0;
        g_T8e[o] = s1;
    }
}

// ---------------------------------------------------------------------------
// K2: per-batch: scan(ek) + window max + A/E scalars + chunk prefixes C0/C1.
//     grid=8, blk=512
// ---------------------------------------------------------------------------
__global__ __launch_bounds__(512, 1)
void k2(void) {
    int b   = blockIdx.x;
    int tid = threadIdx.x;

    __shared__ float sks[LL];
    __shared__ float scan[2][LL];
    __shared__ float cmax[LL/16];
    __shared__ float s8[2][NSC][DD];

    sks[tid]     = g_ks[b*LL + tid];
    scan[0][tid] = g_ek[b*LL + tid];
    __syncthreads();

    if (tid < LL/16) {
        float m = sks[tid*16];
#pragma unroll
        for (int i = 1; i < 16; i++) m = fmaxf(m, sks[tid*16 + i]);
        cmax[tid] = m;
    }

    // superchunk sums from T8
    {
        int g = tid >> 7, d = tid & (DD-1);
#pragma unroll
        for (int q = g; q < NSC; q += 4) {
            float a0 = 0.f, a1 = 0.f;
#pragma unroll
            for (int j = 0; j < 8; j++) {
                a0 += g_T8 [(size_t)(b*NC + q*8 + j)*DD + d];
                a1 += g_T8e[(size_t)(b*NC + q*8 + j)*DD + d];
            }
            s8[0][q][d] = a0;
            s8[1][q][d] = a1;
        }
    }

    // Hillis-Steele inclusive scan of ek (9 steps)
    int cur = 0;
#pragma unroll
    for (int off = 1; off < LL; off <<= 1) {
        __syncthreads();
        float v = scan[cur][tid];
        if (tid >= off) v += scan[cur][tid - off];
        scan[cur ^ 1][tid] = v;
        cur ^= 1;
    }
    __syncthreads();

    // exclusive chunk prefixes: group g handles superchunks 2g, 2g+1
    {
        int g = tid >> 7, d = tid & (DD-1);
#pragma unroll
        for (int ss = 0; ss < 2; ss++) {
            int sc = g*2 + ss;
            float r0 = 0.f, r1 = 0.f;
            for (int q = 0; q < sc; q++) { r0 += s8[0][q][d]; r1 += s8[1][q][d]; }
#pragma unroll
            for (int j = sc*8; j < sc*8 + 8; j++) {
                g_C0[(size_t)(b*(NC+1) + j)*DD + d] = r0;
                g_C1[(size_t)(b*(NC+1) + j)*DD + d] = r1;
                r0 += g_T8 [(size_t)(b*NC + j)*DD + d];
                r1 += g_T8e[(size_t)(b*NC + j)*DD + d];
            }
            if (sc == NSC-1) {
                g_C0[(size_t)(b*(NC+1) + NC)*DD + d] = r0;
                g_C1[(size_t)(b*(NC+1) + NC)*DD + d] = r1;
            }
        }
    }

    // per-query softmax scalars
    {
        int t  = tid;
        int lo = max(0, t - 63);
        int hi = min(LL - 1, t + 64);
        int wc = hi - lo + 1;

        float wm = -INFINITY;
        int c0 = lo >> 4, c1 = hi >> 4;
        int e0 = (c0 + 1) << 4;
        for (int s = lo; s < e0; s++) wm = fmaxf(wm, sks[s]);
        for (int c = c0 + 1; c < c1; c++) wm = fmaxf(wm, cmax[c]);
        for (int s = c1 << 4; s <= hi; s++) wm = fmaxf(wm, sks[s]);

        float qc = g_qs[b*LL + t] + g_c;
        float m  = fmaxf(0.f, qc + wm);     // masked entries score 0, always present
        float A  = expf(qc - m);
        float E  = expf(-m);
        float S1 = scan[cur][hi] - (lo > 0 ? scan[cur][lo-1] : 0.f);
        float Z  = A * S1 + E * (float)(LL - wc) + EPSF;
        float iv = 1.f / Z;
        g_A[b*LL + t] = A * iv;
        g_E[b*LL + t] = E * iv;
    }
}

// ---------------------------------------------------------------------------
// K3f: fused window-sum + output, fully preloaded. Block = (b, 8-query group).
//      grid=512, blk=128.  All loads independent; then pure FMA chain.
// ---------------------------------------------------------------------------
__global__ __launch_bounds__(128)
void k3f(const float* __restrict__ x, float* __restrict__ out) {
    int blk = blockIdx.x;
    int b   = blk >> 6;
    int t0  = (blk & 63) * 8;
    int d   = threadIdx.x;

    bool lo_act = (t0 >= 64);    // else window bottom pinned at 0 for all 8 queries
    bool hi_act = (t0 <= 440);   // else window top pinned at 511 for all 8 queries
    float whi = hi_act ? 1.f : 0.f;
    float wlo = lo_act ? 1.f : 0.f;

    int jh = hi_act ? ((t0 + 64) >> 3) : NC;
    int jl = lo_act ? ((t0 - 64) >> 3) : 0;

    const float* xb  = x + (size_t)b * LL * DD;
    const float* ekb = g_ek + b*LL;
    size_t cbase = (size_t)b * (NC+1) * DD;

    // ---- issue ALL loads up front (independent) ----
    float c0h = __ldg(g_C0 + cbase + (size_t)jh*DD + d);
    float c0l = __ldg(g_C0 + cbase + (size_t)jl*DD + d);
    float c1h = __ldg(g_C1 + cbase + (size_t)jh*DD + d);
    float c1l = __ldg(g_C1 + cbase + (size_t)jl*DD + d);
    float tot = __ldg(g_C0 + cbase + (size_t)NC*DD + d);

    float xh[8], eh[8], xl[8], el[8], Ar[8], Er[8];
#pragma unroll
    for (int i = 0; i < 8; i++) {
        int th = min(t0 + 64 + i, LL - 1);          // clamped: always valid
        int tl = max(t0 - 64 + i, 0);
        xh[i] = __ldg(xb + (size_t)th*DD + d);
        xl[i] = __ldg(xb + (size_t)tl*DD + d);
        eh[i] = __ldg(ekb + th) * whi;              // masked weight
        el[i] = __ldg(ekb + tl) * wlo;
        Ar[i] = __ldg(g_A + b*LL + t0 + i);
        Er[i] = __ldg(g_E + b*LL + t0 + i);
    }

    // ---- pure register compute ----
    float V0 = c0h - c0l;
    float V1 = c1h - c1l;
    float* ob = out + ((size_t)b*LL + t0)*DD + d;

#pragma unroll
    for (int i = 0; i < 8; i++) {
        V0 = fmaf( whi, xh[i], V0);
        V1 = fmaf(eh[i], xh[i], V1);
        V0 = fmaf(-wlo, xl[i], V0);
        V1 = fmaf(-el[i], xl[i], V1);
        ob[(size_t)i*DD] = Ar[i]*V1 + Er[i]*(tot - V0);
    }
}

extern "C" void kernel_launch(void* const* d_in, const int* in_sizes, int n_in,
                              void* d_out, int out_size) {
    const float* x  = (const float*)d_in[0];   // [B,L,D]
    const float* Wt = (const float*)d_in[1];   // [D,U]
    const float* Wx = (const float*)d_in[2];   // [D,U]
    const float* bh = (const float*)d_in[3];   // [U]
    const float* Wa = (const float*)d_in[4];   // [U,1]
    const float* ba = (const float*)d_in[5];   // [1]
    float* out = (float*)d_out;                // [B,L,D]

    k0_fold<<<1, DD>>>(Wt, Wx, bh, Wa, ba);
    k1<<<BB*LL/8, 256>>>(x);
    k2<<<BB, 512>>>();
    k3f<<<BB*NC, DD>>>(x, out);
}

// round 9
// speedup vs baseline: 1.7761x; 1.0120x over previous
#include <cuda_runtime.h>
#include <math.h>

#define BB 8
#define LL 512
#define DD 128
#define UU 32
#define EPSF 1e-7f
#define NC 64            // 8-row chunks per batch
#define NSC 8            // superchunks of 64 rows per batch

// scratch (no allocs allowed)
__device__ float g_qs[BB*LL];
__device__ float g_ks[BB*LL];
__device__ float g_ek[BB*LL];
__device__ float g_T8 [BB*NC*DD];       // 8-row sums of x
__device__ float g_T8e[BB*NC*DD];       // 8-row sums of ek*x
__device__ float g_SO0[BB*(NSC+1)*DD];  // exclusive superchunk offsets of x; [8]=total
__device__ float g_SO1[BB*(NSC+1)*DD];  // exclusive superchunk offsets of ek*x
__device__ float g_A[BB*LL];            // exp(qc-m)/Z
__device__ float g_E[BB*LL];            // exp(-m)/Z

// ---------------------------------------------------------------------------
// K1: per-block coalesced weight fold + warp-per-token scalars + chunk-8 sums.
//     grid=512, blk=256
// ---------------------------------------------------------------------------
__global__ __launch_bounds__(256)
void k1(const float* __restrict__ x,
        const float* __restrict__ Wt, const float* __restrict__ Wx,
        const float* __restrict__ Wa) {
    int warp = threadIdx.x >> 5;
    int lane = threadIdx.x & 31;
    int token = blockIdx.x * 8 + warp;          // 8 consecutive rows, same batch

    __shared__ __align__(16) float swt[DD], swx[DD];
    __shared__ __align__(16) float srow[8*DD];
    __shared__ float sek[8];

    // issue x load first (long latency, overlaps fold)
    const float4* xr = reinterpret_cast<const float4*>(x + (size_t)token * DD);
    float4 xv = xr[lane];
    reinterpret_cast<float4*>(srow)[warp*32 + lane] = xv;

    // coalesced fold: warp w reduces rows w*16 .. w*16+15 of BOTH Wt and Wx
    {
        float wa = __ldg(Wa + lane);
#pragma unroll
        for (int r = 0; r < 16; r++) {
            int row = warp*16 + r;
            float vt = __ldg(Wt + row*UU + lane) * wa;   // consecutive 128B per warp
            float vx = __ldg(Wx + row*UU + lane) * wa;
#pragma unroll
            for (int o = 16; o; o >>= 1) {
                vt += __shfl_down_sync(0xFFFFFFFFu, vt, o);
                vx += __shfl_down_sync(0xFFFFFFFFu, vx, o);
            }
            if (lane == 0) { swt[row] = vt; swx[row] = vx; }
        }
    }
    __syncthreads();

    float4 wt = reinterpret_cast<const float4*>(swt)[lane];
    float4 wx = reinterpret_cast<const float4*>(swx)[lane];
    float q = xv.x*wt.x + xv.y*wt.y + xv.z*wt.z + xv.w*wt.w;
    float k = xv.x*wx.x + xv.y*wx.y + xv.z*wx.z + xv.w*wx.w;
#pragma unroll
    for (int o = 16; o; o >>= 1) {
        q += __shfl_down_sync(0xFFFFFFFFu, q, o);
        k += __shfl_down_sync(0xFFFFFFFFu, k, o);
    }
    if (lane == 0) {
        float e = expf(k);
        g_qs[token] = q;
        g_ks[token] = k;
        g_ek[token] = e;
        sek[warp] = e;
    }
    __syncthreads();

    if (threadIdx.x < DD) {
        int d = threadIdx.x;
        float s0 = 0.f, s1 = 0.f;
#pragma unroll
        for (int w = 0; w < 8; w++) {
            float v = srow[w*DD + d];
            s0 += v;
            s1 = fmaf(sek[w], v, s1);
        }
        size_t o = (size_t)blockIdx.x * DD + d;
        g_T8 [o] = s0;
        g_T8e[o] = s1;
    }
}

// ---------------------------------------------------------------------------
// K2: per-batch: scan(ek) + window max + A/E scalars + superchunk offsets SO.
//     grid=8, blk=512
// ---------------------------------------------------------------------------
__global__ __launch_bounds__(512, 1)
void k2(const float* __restrict__ bh, const float* __restrict__ Wa,
        const float* __restrict__ ba) {
    int b   = blockIdx.x;
    int tid = threadIdx.x;

    __shared__ float sks[LL];
    __shared__ float scan[2][LL];
    __shared__ float cmax[LL/16];
    __shared__ float s8[2][NSC][DD];
    __shared__ float sc_c;

    sks[tid]     = g_ks[b*LL + tid];
    scan[0][tid] = g_ek[b*LL + tid];
    if (tid == 0) {
        float c = __ldg(ba);
#pragma unroll
        for (int u = 0; u < UU; u++) c = fmaf(__ldg(bh + u), __ldg(Wa + u), c);
        sc_c = c;
    }
    __syncthreads();

    if (tid < LL/16) {
        float m = sks[tid*16];
#pragma unroll
        for (int i = 1; i < 16; i++) m = fmaxf(m, sks[tid*16 + i]);
        cmax[tid] = m;
    }

    // superchunk sums from T8
    {
        int g = tid >> 7, d = tid & (DD-1);
#pragma unroll
        for (int q = g; q < NSC; q += 4) {
            float a0 = 0.f, a1 = 0.f;
#pragma unroll
            for (int j = 0; j < 8; j++) {
                a0 += g_T8 [(size_t)(b*NC + q*8 + j)*DD + d];
                a1 += g_T8e[(size_t)(b*NC + q*8 + j)*DD + d];
            }
            s8[0][q][d] = a0;
            s8[1][q][d] = a1;
        }
    }

    // Hillis-Steele inclusive scan of ek (9 steps)
    int cur = 0;
#pragma unroll
    for (int off = 1; off < LL; off <<= 1) {
        __syncthreads();
        float v = scan[cur][tid];
        if (tid >= off) v += scan[cur][tid - off];
        scan[cur ^ 1][tid] = v;
        cur ^= 1;
    }
    __syncthreads();

    // exclusive superchunk offsets (incl. total at [8]) -> global
    if (tid < DD) {
        int d = tid;
        float r0 = 0.f, r1 = 0.f;
#pragma unroll
        for (int sc = 0; sc < NSC; sc++) {
            g_SO0[(size_t)(b*(NSC+1) + sc)*DD + d] = r0;
            g_SO1[(size_t)(b*(NSC+1) + sc)*DD + d] = r1;
            r0 += s8[0][sc][d];
            r1 += s8[1][sc][d];
        }
        g_SO0[(size_t)(b*(NSC+1) + NSC)*DD + d] = r0;
        g_SO1[(size_t)(b*(NSC+1) + NSC)*DD + d] = r1;
    }

    // per-query softmax scalars
    {
        int t  = tid;
        int lo = max(0, t - 63);
        int hi = min(LL - 1, t + 64);
        int wc = hi - lo + 1;

        float wm = -INFINITY;
        int c0 = lo >> 4, c1 = hi >> 4;
        int e0 = (c0 + 1) << 4;
        for (int s = lo; s < e0; s++) wm = fmaxf(wm, sks[s]);
        for (int c = c0 + 1; c < c1; c++) wm = fmaxf(wm, cmax[c]);
        for (int s = c1 << 4; s <= hi; s++) wm = fmaxf(wm, sks[s]);

        float qc = g_qs[b*LL + t] + sc_c;
        float m  = fmaxf(0.f, qc + wm);     // masked entries score 0, always present
        float A  = expf(qc - m);
        float E  = expf(-m);
        float S1 = scan[cur][hi] - (lo > 0 ? scan[cur][lo-1] : 0.f);
        float Z  = A * S1 + E * (float)(LL - wc) + EPSF;
        float iv = 1.f / Z;
        g_A[b*LL + t] = A * iv;
        g_E[b*LL + t] = E * iv;
    }
}

// ---------------------------------------------------------------------------
// K3f: fused window-sum + output, fully preloaded; C values rebuilt from
//      SO + <=7 T8 rows per end. Block = (b, 8-query group). grid=512, blk=128
// ---------------------------------------------------------------------------
__global__ __launch_bounds__(128)
void k3f(const float* __restrict__ x, float* __restrict__ out) {
    int blk = blockIdx.x;
    int b   = blk >> 6;
    int t0  = (blk & 63) * 8;
    int d   = threadIdx.x;

    bool lo_act = (t0 >= 64);    // else window bottom pinned at 0 for all 8 queries
    bool hi_act = (t0 <= 440);   // else window top pinned at 511 for all 8 queries
    float whi = hi_act ? 1.f : 0.f;
    float wlo = lo_act ? 1.f : 0.f;

    int jh = hi_act ? ((t0 >> 3) + 8) : NC;   // chunk index of window top
    int jl = lo_act ? ((t0 >> 3) - 8) : 0;    // chunk index of window bottom
    int sc_h = jh >> 3, r_h = jh & 7;
    int sc_l = jl >> 3, r_l = jl & 7;

    const float* xb  = x + (size_t)b * LL * DD;
    const float* ekb = g_ek + b*LL;
    size_t sobase = (size_t)b * (NSC+1) * DD;
    size_t t8base = (size_t)b * NC;

    // ---- issue ALL loads up front (independent; predicated T8 hops) ----
    float c0h = __ldg(g_SO0 + sobase + (size_t)sc_h*DD + d);
    float c1h = __ldg(g_SO1 + sobase + (size_t)sc_h*DD + d);
    float c0l = __ldg(g_SO0 + sobase + (size_t)sc_l*DD + d);
    float c1l = __ldg(g_SO1 + sobase + (size_t)sc_l*DD + d);
    float tot = __ldg(g_SO0 + sobase + (size_t)NSC*DD + d);

#pragma unroll
    for (int j = 0; j < 7; j++) {
        if (j < r_h) {
            c0h += __ldg(g_T8  + (size_t)(t8base + sc_h*8 + j)*DD + d);
            c1h += __ldg(g_T8e + (size_t)(t8base + sc_h*8 + j)*DD + d);
        }
        if (j < r_l) {
            c0l += __ldg(g_T8  + (size_t)(t8base + sc_l*8 + j)*DD + d);
            c1l += __ldg(g_T8e + (size_t)(t8base + sc_l*8 + j)*DD + d);
        }
    }

    float xh[8], eh[8], xl[8], el[8], Ar[8], Er[8];
#pragma unroll
    for (int i = 0; i < 8; i++) {
        int th = min(t0 + 64 + i, LL - 1);          // clamped: always valid
        int tl = max(t0 - 64 + i, 0);
        xh[i] = __ldg(xb + (size_t)th*DD + d);
        xl[i] = __ldg(xb + (size_t)tl*DD + d);
        eh[i] = __ldg(ekb + th) * whi;              // masked weight
        el[i] = __ldg(ekb + tl) * wlo;
        Ar[i] = __ldg(g_A + b*LL + t0 + i);
        Er[i] = __ldg(g_E + b*LL + t0 + i);
    }

    // ---- pure register compute ----
    float V0 = c0h - c0l;
    float V1 = c1h - c1l;
    float* ob = out + ((size_t)b*LL + t0)*DD + d;

#pragma unroll
    for (int i = 0; i < 8; i++) {
        V0 = fmaf( whi, xh[i], V0);
        V1 = fmaf(eh[i], xh[i], V1);
        V0 = fmaf(-wlo, xl[i], V0);
        V1 = fmaf(-el[i], xl[i], V1);
        ob[(size_t)i*DD] = Ar[i]*V1 + Er[i]*(tot - V0);
    }
}

extern "C" void kernel_launch(void* const* d_in, const int* in_sizes, int n_in,
                              void* d_out, int out_size) {
    const float* x  = (const float*)d_in[0];   // [B,L,D]
    const float* Wt = (const float*)d_in[1];   // [D,U]
    const float* Wx = (const float*)d_in[2];   // [D,U]
    const float* bh = (const float*)d_in[3];   // [U]
    const float* Wa = (const float*)d_in[4];   // [U,1]
    const float* ba = (const float*)d_in[5];   // [1]
    float* out = (float*)d_out;                // [B,L,D]

    k1<<<BB*LL/8, 256>>>(x, Wt, Wx, Wa);
    k2<<<BB, 512>>>(bh, Wa, ba);
    k3f<<<BB*NC, DD>>>(x, out);
}

// round 10
// speedup vs baseline: 1.9715x; 1.1101x over previous
#include <cuda_runtime.h>
#include <math.h>

#define BB 8
#define LL 512
#define DD 128
#define UU 32
#define EPSF 1e-7f
#define NC 64            // 8-row chunks per batch
#define NSC 8            // superchunks of 64 rows per batch
#define WPAD 33          // padded row stride for conflict-free smem weights

// scratch (no allocs allowed)
__device__ float g_qs[BB*LL];
__device__ float g_ks[BB*LL];
__device__ float g_ek[BB*LL];
__device__ float g_T8 [BB*NC*DD];       // 8-row sums of x
__device__ float g_T8e[BB*NC*DD];       // 8-row sums of ek*x
__device__ float g_SO0[BB*(NSC+1)*DD];  // exclusive superchunk offsets of x; [8]=total
__device__ float g_SO1[BB*(NSC+1)*DD];  // exclusive superchunk offsets of ek*x
__device__ float g_A[BB*LL];            // exp(qc-m)/Z
__device__ float g_E[BB*LL];            // exp(-m)/Z

// ---------------------------------------------------------------------------
// K1: smem-staged weight fold + warp-per-token scalars + chunk-8 sums.
//     grid=512, blk=256
// ---------------------------------------------------------------------------
__global__ __launch_bounds__(256)
void k1(const float* __restrict__ x,
        const float* __restrict__ Wt, const float* __restrict__ Wx,
        const float* __restrict__ Wa) {
    int tid  = threadIdx.x;
    int warp = tid >> 5;
    int lane = tid & 31;
    int token = blockIdx.x * 8 + warp;          // 8 consecutive rows, same batch

    __shared__ float sWt[DD*WPAD], sWx[DD*WPAD];
    __shared__ float sWa[UU];
    __shared__ __align__(16) float swt[DD], swx[DD];
    __shared__ __align__(16) float srow[8*DD];
    __shared__ float sek[8];

    // issue x load first (long latency, overlaps weight staging)
    const float4* xr = reinterpret_cast<const float4*>(x + (size_t)token * DD);
    float4 xv = xr[lane];
    reinterpret_cast<float4*>(srow)[warp*32 + lane] = xv;

    // stage weights coalesced into padded smem (4 float4 per thread per matrix)
    {
        const float4* Wt4 = reinterpret_cast<const float4*>(Wt);
        const float4* Wx4 = reinterpret_cast<const float4*>(Wx);
#pragma unroll
        for (int i = 0; i < 4; i++) {
            int idx = tid + i*256;              // float4 index 0..1023
            int row = idx >> 3;                 // 8 float4 per 32-float row
            int col = (idx & 7) * 4;
            float4 vt = __ldg(Wt4 + idx);
            float4 vx = __ldg(Wx4 + idx);
            float* dt = &sWt[row*WPAD + col];
            float* dx = &sWx[row*WPAD + col];
            dt[0]=vt.x; dt[1]=vt.y; dt[2]=vt.z; dt[3]=vt.w;
            dx[0]=vx.x; dx[1]=vx.y; dx[2]=vx.z; dx[3]=vx.w;
        }
        if (tid < UU) sWa[tid] = __ldg(Wa + tid);
    }
    __syncthreads();

    // fold: thread d computes swt[d], swx[d] (conflict-free: (33d+u)%32 = (d+u)%32)
    if (tid < DD) {
        float at = 0.f, ax = 0.f;
#pragma unroll
        for (int u = 0; u < UU; u++) {
            float wa = sWa[u];
            at = fmaf(sWt[tid*WPAD + u], wa, at);
            ax = fmaf(sWx[tid*WPAD + u], wa, ax);
        }
        swt[tid] = at;
        swx[tid] = ax;
    }
    __syncthreads();

    float4 wt = reinterpret_cast<const float4*>(swt)[lane];
    float4 wx = reinterpret_cast<const float4*>(swx)[lane];
    float q = xv.x*wt.x + xv.y*wt.y + xv.z*wt.z + xv.w*wt.w;
    float k = xv.x*wx.x + xv.y*wx.y + xv.z*wx.z + xv.w*wx.w;
#pragma unroll
    for (int o = 16; o; o >>= 1) {
        q += __shfl_down_sync(0xFFFFFFFFu, q, o);
        k += __shfl_down_sync(0xFFFFFFFFu, k, o);
    }
    if (lane == 0) {
        float e = expf(k);
        g_qs[token] = q;
        g_ks[token] = k;
        g_ek[token] = e;
        sek[warp] = e;
    }
    __syncthreads();

    if (tid < DD) {
        int d = tid;
        float s0 = 0.f, s1 = 0.f;
#pragma unroll
        for (int w = 0; w < 8; w++) {
            float v = srow[w*DD + d];
            s0 += v;
            s1 = fmaf(sek[w], v, s1);
        }
        size_t o = (size_t)blockIdx.x * DD + d;
        g_T8 [o] = s0;
        g_T8e[o] = s1;
    }
}

// ---------------------------------------------------------------------------
// K2: per-batch: scan(ek) + window max + A/E scalars + superchunk offsets SO.
//     grid=8, blk=512
// ---------------------------------------------------------------------------
__global__ __launch_bounds__(512, 1)
void k2(const float* __restrict__ bh, const float* __restrict__ Wa,
        const float* __restrict__ ba) {
    int b   = blockIdx.x;
    int tid = threadIdx.x;

    __shared__ float sks[LL];
    __shared__ float scan[2][LL];
    __shared__ float cmax[LL/16];
    __shared__ float s8[2][NSC][DD];
    __shared__ float sc_c;

    sks[tid]     = g_ks[b*LL + tid];
    scan[0][tid] = g_ek[b*LL + tid];
    if (tid == 0) {
        float c = __ldg(ba);
#pragma unroll
        for (int u = 0; u < UU; u++) c = fmaf(__ldg(bh + u), __ldg(Wa + u), c);
        sc_c = c;
    }
    __syncthreads();

    if (tid < LL/16) {
        float m = sks[tid*16];
#pragma unroll
        for (int i = 1; i < 16; i++) m = fmaxf(m, sks[tid*16 + i]);
        cmax[tid] = m;
    }

    // superchunk sums from T8
    {
        int g = tid >> 7, d = tid & (DD-1);
#pragma unroll
        for (int q = g; q < NSC; q += 4) {
            float a0 = 0.f, a1 = 0.f;
#pragma unroll
            for (int j = 0; j < 8; j++) {
                a0 += g_T8 [(size_t)(b*NC + q*8 + j)*DD + d];
                a1 += g_T8e[(size_t)(b*NC + q*8 + j)*DD + d];
            }
            s8[0][q][d] = a0;
            s8[1][q][d] = a1;
        }
    }

    // Hillis-Steele inclusive scan of ek (9 steps)
    int cur = 0;
#pragma unroll
    for (int off = 1; off < LL; off <<= 1) {
        __syncthreads();
        float v = scan[cur][tid];
        if (tid >= off) v += scan[cur][tid - off];
        scan[cur ^ 1][tid] = v;
        cur ^= 1;
    }
    __syncthreads();

    // exclusive superchunk offsets (incl. total at [8]) -> global
    if (tid < DD) {
        int d = tid;
        float r0 = 0.f, r1 = 0.f;
#pragma unroll
        for (int sc = 0; sc < NSC; sc++) {
            g_SO0[(size_t)(b*(NSC+1) + sc)*DD + d] = r0;
            g_SO1[(size_t)(b*(NSC+1) + sc)*DD + d] = r1;
            r0 += s8[0][sc][d];
            r1 += s8[1][sc][d];
        }
        g_SO0[(size_t)(b*(NSC+1) + NSC)*DD + d] = r0;
        g_SO1[(size_t)(b*(NSC+1) + NSC)*DD + d] = r1;
    }

    // per-query softmax scalars
    {
        int t  = tid;
        int lo = max(0, t - 63);
        int hi = min(LL - 1, t + 64);
        int wc = hi - lo + 1;

        float wm = -INFINITY;
        int c0 = lo >> 4, c1 = hi >> 4;
        int e0 = (c0 + 1) << 4;
        for (int s = lo; s < e0; s++) wm = fmaxf(wm, sks[s]);
        for (int c = c0 + 1; c < c1; c++) wm = fmaxf(wm, cmax[c]);
        for (int s = c1 << 4; s <= hi; s++) wm = fmaxf(wm, sks[s]);

        float qc = g_qs[b*LL + t] + sc_c;
        float m  = fmaxf(0.f, qc + wm);     // masked entries score 0, always present
        float A  = expf(qc - m);
        float E  = expf(-m);
        float S1 = scan[cur][hi] - (lo > 0 ? scan[cur][lo-1] : 0.f);
        float Z  = A * S1 + E * (float)(LL - wc) + EPSF;
        float iv = 1.f / Z;
        g_A[b*LL + t] = A * iv;
        g_E[b*LL + t] = E * iv;
    }
}

// ---------------------------------------------------------------------------
// K3f: fused window-sum + output, fully preloaded; C values rebuilt from
//      SO + <=7 T8 rows per end. Block = (b, 8-query group). grid=512, blk=128
// ---------------------------------------------------------------------------
__global__ __launch_bounds__(128)
void k3f(const float* __restrict__ x, float* __restrict__ out) {
    int blk = blockIdx.x;
    int b   = blk >> 6;
    int t0  = (blk & 63) * 8;
    int d   = threadIdx.x;

    bool lo_act = (t0 >= 64);    // else window bottom pinned at 0 for all 8 queries
    bool hi_act = (t0 <= 440);   // else window top pinned at 511 for all 8 queries
    float whi = hi_act ? 1.f : 0.f;
    float wlo = lo_act ? 1.f : 0.f;

    int jh = hi_act ? ((t0 >> 3) + 8) : NC;   // chunk index of window top
    int jl = lo_act ? ((t0 >> 3) - 8) : 0;    // chunk index of window bottom
    int sc_h = jh >> 3, r_h = jh & 7;
    int sc_l = jl >> 3, r_l = jl & 7;

    const float* xb  = x + (size_t)b * LL * DD;
    const float* ekb = g_ek + b*LL;
    size_t sobase = (size_t)b * (NSC+1) * DD;
    size_t t8base = (size_t)b * NC;

    // ---- issue ALL loads up front (independent; predicated T8 hops) ----
    float c0h = __ldg(g_SO0 + sobase + (size_t)sc_h*DD + d);
    float c1h = __ldg(g_SO1 + sobase + (size_t)sc_h*DD + d);
    float c0l = __ldg(g_SO0 + sobase + (size_t)sc_l*DD + d);
    float c1l = __ldg(g_SO1 + sobase + (size_t)sc_l*DD + d);
    float tot = __ldg(g_SO0 + sobase + (size_t)NSC*DD + d);

#pragma unroll
    for (int j = 0; j < 7; j++) {
        if (j < r_h) {
            c0h += __ldg(g_T8  + (size_t)(t8base + sc_h*8 + j)*DD + d);
            c1h += __ldg(g_T8e + (size_t)(t8base + sc_h*8 + j)*DD + d);
        }
        if (j < r_l) {
            c0l += __ldg(g_T8  + (size_t)(t8base + sc_l*8 + j)*DD + d);
            c1l += __ldg(g_T8e + (size_t)(t8base + sc_l*8 + j)*DD + d);
        }
    }

    float xh[8], eh[8], xl[8], el[8], Ar[8], Er[8];
#pragma unroll
    for (int i = 0; i < 8; i++) {
        int th = min(t0 + 64 + i, LL - 1);          // clamped: always valid
        int tl = max(t0 - 64 + i, 0);
        xh[i] = __ldg(xb + (size_t)th*DD + d);
        xl[i] = __ldg(xb + (size_t)tl*DD + d);
        eh[i] = __ldg(ekb + th) * whi;              // masked weight
        el[i] = __ldg(ekb + tl) * wlo;
        Ar[i] = __ldg(g_A + b*LL + t0 + i);
        Er[i] = __ldg(g_E + b*LL + t0 + i);
    }

    // ---- pure register compute ----
    float V0 = c0h - c0l;
    float V1 = c1h - c1l;
    float* ob = out + ((size_t)b*LL + t0)*DD + d;

#pragma unroll
    for (int i = 0; i < 8; i++) {
        V0 = fmaf( whi, xh[i], V0);
        V1 = fmaf(eh[i], xh[i], V1);
        V0 = fmaf(-wlo, xl[i], V0);
        V1 = fmaf(-el[i], xl[i], V1);
        ob[(size_t)i*DD] = Ar[i]*V1 + Er[i]*(tot - V0);
    }
}

extern "C" void kernel_launch(void* const* d_in, const int* in_sizes, int n_in,
                              void* d_out, int out_size) {
    const float* x  = (const float*)d_in[0];   // [B,L,D]
    const float* Wt = (const float*)d_in[1];   // [D,U]
    const float* Wx = (const float*)d_in[2];   // [D,U]
    const float* bh = (const float*)d_in[3];   // [U]
    const float* Wa = (const float*)d_in[4];   // [U,1]
    const float* ba = (const float*)d_in[5];   // [1]
    float* out = (float*)d_out;                // [B,L,D]

    k1<<<BB*LL/8, 256>>>(x, Wt, Wx, Wa);
    k2<<<BB, 512>>>(bh, Wa, ba);
    k3f<<<BB*NC, DD>>>(x, out);
}

// round 11
// speedup vs baseline: 2.2392x; 1.1358x over previous
#include <cuda_runtime.h>
#include <math.h>

#define BB 8
#define LL 512
#define DD 128
#define UU 32
#define EPSF 1e-7f
#define NC 64            // 8-row chunks per batch
#define NSC 8            // superchunks of 64 rows per batch

// scratch (no allocs allowed)
__device__ float g_qs[BB*LL];
__device__ float g_ks[BB*LL];
__device__ float g_ek[BB*LL];
__device__ float g_T8 [BB*NC*DD];       // 8-row sums of x
__device__ float g_T8e[BB*NC*DD];       // 8-row sums of ek*x
__device__ float g_SO0[BB*(NSC+1)*DD];  // exclusive superchunk offsets of x; [8]=total
__device__ float g_SO1[BB*(NSC+1)*DD];  // exclusive superchunk offsets of ek*x
__device__ float g_A[BB*LL];            // exp(qc-m)/Z
__device__ float g_E[BB*LL];            // exp(-m)/Z

// ---------------------------------------------------------------------------
// K1: register weight fold (width-8 shfl reduce) + warp-per-token scalars +
//     chunk-8 sums. grid=512, blk=256
// ---------------------------------------------------------------------------
__global__ __launch_bounds__(256)
void k1(const float* __restrict__ x,
        const float* __restrict__ Wt, const float* __restrict__ Wx,
        const float* __restrict__ Wa) {
    int tid  = threadIdx.x;
    int warp = tid >> 5;
    int lane = tid & 31;
    int token = blockIdx.x * 8 + warp;          // 8 consecutive rows, same batch

    __shared__ __align__(16) float swt[DD], swx[DD];
    __shared__ __align__(16) float srow[8*DD];
    __shared__ float sek[8];

    // issue x load first (long latency, overlaps fold)
    const float4* xr = reinterpret_cast<const float4*>(x + (size_t)token * DD);
    float4 xv = xr[lane];
    reinterpret_cast<float4*>(srow)[warp*32 + lane] = xv;

    // fold with zero smem staging:
    // thread's u-group is fixed: ug = tid&7; row(i) = (tid + 256*i) >> 3.
    {
        int ug = tid & 7;
        float4 wa = reinterpret_cast<const float4*>(Wa)[ug];
        const float4* Wt4 = reinterpret_cast<const float4*>(Wt);
        const float4* Wx4 = reinterpret_cast<const float4*>(Wx);
#pragma unroll
        for (int i = 0; i < 4; i++) {
            int idx = tid + i*256;
            int row = idx >> 3;
            float4 vt = __ldg(Wt4 + idx);
            float4 vx = __ldg(Wx4 + idx);
            float pt = vt.x*wa.x + vt.y*wa.y + vt.z*wa.z + vt.w*wa.w;
            float px = vx.x*wa.x + vx.y*wa.y + vx.z*wa.z + vx.w*wa.w;
#pragma unroll
            for (int o = 4; o; o >>= 1) {       // reduce across 8-lane row group
                pt += __shfl_down_sync(0xFFFFFFFFu, pt, o, 8);
                px += __shfl_down_sync(0xFFFFFFFFu, px, o, 8);
            }
            if (ug == 0) { swt[row] = pt; swx[row] = px; }
        }
    }
    __syncthreads();

    float4 wt = reinterpret_cast<const float4*>(swt)[lane];
    float4 wx = reinterpret_cast<const float4*>(swx)[lane];
    float q = xv.x*wt.x + xv.y*wt.y + xv.z*wt.z + xv.w*wt.w;
    float k = xv.x*wx.x + xv.y*wx.y + xv.z*wx.z + xv.w*wx.w;
#pragma unroll
    for (int o = 16; o; o >>= 1) {
        q += __shfl_down_sync(0xFFFFFFFFu, q, o);
        k += __shfl_down_sync(0xFFFFFFFFu, k, o);
    }
    if (lane == 0) {
        float e = expf(k);
        g_qs[token] = q;
        g_ks[token] = k;
        g_ek[token] = e;
        sek[warp] = e;
    }
    __syncthreads();

    if (tid < DD) {
        int d = tid;
        float s0 = 0.f, s1 = 0.f;
#pragma unroll
        for (int w = 0; w < 8; w++) {
            float v = srow[w*DD + d];
            s0 += v;
            s1 = fmaf(sek[w], v, s1);
        }
        size_t o = (size_t)blockIdx.x * DD + d;
        g_T8 [o] = s0;
        g_T8e[o] = s1;
    }
}

// ---------------------------------------------------------------------------
// K2: per-batch: scan(ek) + window max + A/E scalars + superchunk offsets SO.
//     grid=8, blk=512
// ---------------------------------------------------------------------------
__global__ __launch_bounds__(512, 1)
void k2(const float* __restrict__ bh, const float* __restrict__ Wa,
        const float* __restrict__ ba) {
    int b   = blockIdx.x;
    int tid = threadIdx.x;

    __shared__ float sks[LL];
    __shared__ float scan[2][LL];
    __shared__ float cmax[LL/16];
    __shared__ float s8[2][NSC][DD];
    __shared__ float sc_c;

    sks[tid]     = g_ks[b*LL + tid];
    scan[0][tid] = g_ek[b*LL + tid];
    if (tid == 0) {
        float c = __ldg(ba);
#pragma unroll
        for (int u = 0; u < UU; u++) c = fmaf(__ldg(bh + u), __ldg(Wa + u), c);
        sc_c = c;
    }
    __syncthreads();

    if (tid < LL/16) {
        float m = sks[tid*16];
#pragma unroll
        for (int i = 1; i < 16; i++) m = fmaxf(m, sks[tid*16 + i]);
        cmax[tid] = m;
    }

    // superchunk sums from T8
    {
        int g = tid >> 7, d = tid & (DD-1);
#pragma unroll
        for (int q = g; q < NSC; q += 4) {
            float a0 = 0.f, a1 = 0.f;
#pragma unroll
            for (int j = 0; j < 8; j++) {
                a0 += g_T8 [(size_t)(b*NC + q*8 + j)*DD + d];
                a1 += g_T8e[(size_t)(b*NC + q*8 + j)*DD + d];
            }
            s8[0][q][d] = a0;
            s8[1][q][d] = a1;
        }
    }

    // Hillis-Steele inclusive scan of ek (9 steps)
    int cur = 0;
#pragma unroll
    for (int off = 1; off < LL; off <<= 1) {
        __syncthreads();
        float v = scan[cur][tid];
        if (tid >= off) v += scan[cur][tid - off];
        scan[cur ^ 1][tid] = v;
        cur ^= 1;
    }
    __syncthreads();

    // exclusive superchunk offsets (incl. total at [8]) -> global
    if (tid < DD) {
        int d = tid;
        float r0 = 0.f, r1 = 0.f;
#pragma unroll
        for (int sc = 0; sc < NSC; sc++) {
            g_SO0[(size_t)(b*(NSC+1) + sc)*DD + d] = r0;
            g_SO1[(size_t)(b*(NSC+1) + sc)*DD + d] = r1;
            r0 += s8[0][sc][d];
            r1 += s8[1][sc][d];
        }
        g_SO0[(size_t)(b*(NSC+1) + NSC)*DD + d] = r0;
        g_SO1[(size_t)(b*(NSC+1) + NSC)*DD + d] = r1;
    }

    // per-query softmax scalars
    {
        int t  = tid;
        int lo = max(0, t - 63);
        int hi = min(LL - 1, t + 64);
        int wc = hi - lo + 1;

        float wm = -INFINITY;
        int c0 = lo >> 4, c1 = hi >> 4;
        int e0 = (c0 + 1) << 4;
        for (int s = lo; s < e0; s++) wm = fmaxf(wm, sks[s]);
        for (int c = c0 + 1; c < c1; c++) wm = fmaxf(wm, cmax[c]);
        for (int s = c1 << 4; s <= hi; s++) wm = fmaxf(wm, sks[s]);

        float qc = g_qs[b*LL + t] + sc_c;
        float m  = fmaxf(0.f, qc + wm);     // masked entries score 0, always present
        float A  = expf(qc - m);
        float E  = expf(-m);
        float S1 = scan[cur][hi] - (lo > 0 ? scan[cur][lo-1] : 0.f);
        float Z  = A * S1 + E * (float)(LL - wc) + EPSF;
        float iv = 1.f / Z;
        g_A[b*LL + t] = A * iv;
        g_E[b*LL + t] = E * iv;
    }
}

// ---------------------------------------------------------------------------
// K3f: fused window-sum + output, fully preloaded; C values rebuilt from
//      SO + <=7 T8 rows per end. Block = (b, 8-query group). grid=512, blk=128
// ---------------------------------------------------------------------------
__global__ __launch_bounds__(128)
void k3f(const float* __restrict__ x, float* __restrict__ out) {
    int blk = blockIdx.x;
    int b   = blk >> 6;
    int t0  = (blk & 63) * 8;
    int d   = threadIdx.x;

    bool lo_act = (t0 >= 64);    // else window bottom pinned at 0 for all 8 queries
    bool hi_act = (t0 <= 440);   // else window top pinned at 511 for all 8 queries
    float whi = hi_act ? 1.f : 0.f;
    float wlo = lo_act ? 1.f : 0.f;

    int jh = hi_act ? ((t0 >> 3) + 8) : NC;   // chunk index of window top
    int jl = lo_act ? ((t0 >> 3) - 8) : 0;    // chunk index of window bottom
    int sc_h = jh >> 3, r_h = jh & 7;
    int sc_l = jl >> 3, r_l = jl & 7;

    const float* xb  = x + (size_t)b * LL * DD;
    const float* ekb = g_ek + b*LL;
    size_t sobase = (size_t)b * (NSC+1) * DD;
    size_t t8base = (size_t)b * NC;

    // ---- issue ALL loads up front (independent; predicated T8 hops) ----
    float c0h = __ldg(g_SO0 + sobase + (size_t)sc_h*DD + d);
    float c1h = __ldg(g_SO1 + sobase + (size_t)sc_h*DD + d);
    float c0l = __ldg(g_SO0 + sobase + (size_t)sc_l*DD + d);
    float c1l = __ldg(g_SO1 + sobase + (size_t)sc_l*DD + d);
    float tot = __ldg(g_SO0 + sobase + (size_t)NSC*DD + d);

#pragma unroll
    for (int j = 0; j < 7; j++) {
        if (j < r_h) {
            c0h += __ldg(g_T8  + (size_t)(t8base + sc_h*8 + j)*DD + d);
            c1h += __ldg(g_T8e + (size_t)(t8base + sc_h*8 + j)*DD + d);
        }
        if (j < r_l) {
            c0l += __ldg(g_T8  + (size_t)(t8base + sc_l*8 + j)*DD + d);
            c1l += __ldg(g_T8e + (size_t)(t8base + sc_l*8 + j)*DD + d);
        }
    }

    float xh[8], eh[8], xl[8], el[8], Ar[8], Er[8];
#pragma unroll
    for (int i = 0; i < 8; i++) {
        int th = min(t0 + 64 + i, LL - 1);          // clamped: always valid
        int tl = max(t0 - 64 + i, 0);
        xh[i] = __ldg(xb + (size_t)th*DD + d);
        xl[i] = __ldg(xb + (size_t)tl*DD + d);
        eh[i] = __ldg(ekb + th) * whi;              // masked weight
        el[i] = __ldg(ekb + tl) * wlo;
        Ar[i] = __ldg(g_A + b*LL + t0 + i);
        Er[i] = __ldg(g_E + b*LL + t0 + i);
    }

    // ---- pure register compute ----
    float V0 = c0h - c0l;
    float V1 = c1h - c1l;
    float* ob = out + ((size_t)b*LL + t0)*DD + d;

#pragma unroll
    for (int i = 0; i < 8; i++) {
        V0 = fmaf( whi, xh[i], V0);
        V1 = fmaf(eh[i], xh[i], V1);
        V0 = fmaf(-wlo, xl[i], V0);
        V1 = fmaf(-el[i], xl[i], V1);
        ob[(size_t)i*DD] = Ar[i]*V1 + Er[i]*(tot - V0);
    }
}

extern "C" void kernel_launch(void* const* d_in, const int* in_sizes, int n_in,
                              void* d_out, int out_size) {
    const float* x  = (const float*)d_in[0];   // [B,L,D]
    const float* Wt = (const float*)d_in[1];   // [D,U]
    const float* Wx = (const float*)d_in[2];   // [D,U]
    const float* bh = (const float*)d_in[3];   // [U]
    const float* Wa = (const float*)d_in[4];   // [U,1]
    const float* ba = (const float*)d_in[5];   // [1]
    float* out = (float*)d_out;                // [B,L,D]

    k1<<<BB*LL/8, 256>>>(x, Wt, Wx, Wa);
    k2<<<BB, 512>>>(bh, Wa, ba);
    k3f<<<BB*NC, DD>>>(x, out);
}